// round 15
// baseline (speedup 1.0000x reference)
#include <cuda_runtime.h>
#include <cstdint>
#include <cstddef>

#define TT 512
#define CC 128
#define LL 80
#define BLANKC 127
#define FEPS 1e-7f
#define FULLM 0xffffffffu
#define RING 48
#define NGRP 5
#define PRIME 40

__device__ __forceinline__ void cp_async16(void* smem, const void* gmem) {
    unsigned s = (unsigned)__cvta_generic_to_shared(smem);
    asm volatile("cp.async.ca.shared.global [%0], [%1], 16;\n" :: "r"(s), "l"(gmem));
}
__device__ __forceinline__ void cp_commit() {
    asm volatile("cp.async.commit_group;\n" ::: "memory");
}
__device__ __forceinline__ void cp_waitg() {
    asm volatile("cp.async.wait_group %0;\n" :: "n"(NGRP - 1) : "memory");
}

// 128 blocks x 128 threads: one warp per SMSP, one batch element per warp.
// R13 architecture (cp.async smem ring, all row reads via LDS, gather
// prefetch one step ahead, rotate-shfl recursion, linear domain + 8-step
// lagged rescale, 5-stage pipelined norm butterfly) with:
//  (a) RING 48 / 5 commit groups in flight — group-wait cover (40 steps)
//      far exceeds loaded memory latency, so waits never bind as the step
//      time shrinks;
//  (b) refill spread to ONE cp.async per step (commit once per 8 steps;
//      identical group semantics / hazard distances) — removes the
//      boundary LSU+L1 burst;
//  (c) pointer-increment ring addressing (no per-step %RING / IMAD).
// States: e_i = alpha[2i] (blank, i=0..80) lane i%32 reg i/32;
//         o_i = alpha[2i+1] (label, i=0..79) likewise.
__global__ void __launch_bounds__(128, 1) ctc_kernel(
    const int* __restrict__ lab32,
    const float* __restrict__ ypred,
    float* __restrict__ out)
{
    extern __shared__ __align__(16) float ring[];   // [4][RING][CC] = 96 KB
    const int lane = threadIdx.x & 31;
    const int w = threadIdx.x >> 5;
    const int b = blockIdx.x * 4 + w;
    const int lanem1 = (lane + 31) & 31;
    float* __restrict__ rw = ring + (size_t)w * RING * CC;
    const float* __restrict__ yb = ypred + (size_t)b * (TT * CC);

    // detect label element width (int64 little-endian vs int32)
    int probe = lab32[1] | lab32[3] | lab32[5] | lab32[7]
              | lab32[9] | lab32[11] | lab32[13] | lab32[15];
    const int stride = (probe == 0) ? 2 : 1;
    const int* lb = lab32 + (size_t)b * LL * stride;

    const int i1 = 32 + lane, i2 = 64 + lane;
    const int L0 = lb[lane * stride];
    const int L1 = lb[i1 * stride];
    const bool v2 = (i2 < LL);
    const int L2 = v2 ? lb[i2 * stride] : BLANKC;
    const float al0 = (lane == 0) ? 0.f : ((L0 != lb[(lane - 1) * stride]) ? 1.f : 0.f);
    const float al1 = (L1 != lb[(i1 - 1) * stride]) ? 1.f : 0.f;
    const float al2 = (v2 && (L2 != lb[(i2 - 1) * stride])) ? 1.f : 0.f;

    // prime NGRP groups: rows 0..PRIME-1
#pragma unroll
    for (int g = 0; g < NGRP; g++) {
#pragma unroll
        for (int r = 0; r < 8; r++) {
            int row = g * 8 + r;
            cp_async16(rw + row * CC + lane * 4, yb + (size_t)row * CC + lane * 4);
        }
        cp_commit();
    }

    float e0 = 0.f, e1 = 0.f, e2 = 0.f, o0 = 0.f, o1 = 0.f, o2 = 0.f;
    float np0 = 0.f, np1 = 0.f, np2 = 0.f, np3 = 0.f, np4 = 0.f;
    float accN0 = 0.f, accN1 = 0.f, accS = 0.f;
    float rs = 0.f, pend = 0.f, cN = 1.f;
    float pB = 0.f, p0 = 0.f, p1 = 0.f, p2 = 0.f;   // gather prefetch regs
    const float* rp = rw;                            // read ptr: slot of row t
    float* wp = rw + PRIME * CC;                     // write ptr: slot of row t+PRIME
    const float* const rlast = rw + (RING - 1) * CC;
    int t = 0;

#define CTC_STEP(FIRST, U) do {                                                     \
    float yB, y0, y1, y2;                                                           \
    if ((U) == 0) {                                                                 \
        cp_waitg();                                                                 \
        __syncwarp();                                                               \
        yB = rp[BLANKC] + FEPS;                                                     \
        y0 = rp[L0] + FEPS;                                                         \
        y1 = rp[L1] + FEPS;                                                         \
        y2 = v2 ? (rp[L2] + FEPS) : 0.f;                                            \
    } else {                                                                        \
        yB = pB + FEPS;                                                             \
        y0 = p0 + FEPS;                                                             \
        y1 = p1 + FEPS;                                                             \
        y2 = v2 ? (p2 + FEPS) : 0.f;                                                \
    }                                                                               \
    /* spread refill: one row per step; commit once per 8 steps */                  \
    { int tn = t + PRIME;                                                           \
      if (tn < TT) cp_async16(wp + lane * 4, yb + (size_t)tn * CC + lane * 4);      \
      wp = (wp == rlast) ? (float*)rw : wp + CC; }                                  \
    if ((U) == 7) cp_commit();                                                      \
    const float* rn = (rp == rlast) ? rw : rp + CC;                                 \
    if ((U) < 7) {                                                                  \
        pB = rn[BLANKC]; p0 = rn[L0]; p1 = rn[L1]; p2 = rn[L2];                     \
    }                                                                               \
    float4 v4 = *(const float4*)(rp + lane * 4);                                    \
    float loc = (v4.x + v4.y) + (v4.z + v4.w);                                      \
    /* norm pipeline: finish row t-5 */                                             \
    if (!(FIRST) || (U) >= 5) {                                                     \
        float fin = np4 + __shfl_xor_sync(FULLM, np4, 1);                           \
        float lg = __logf(fin + (float)CC * FEPS);                                  \
        if (((U) & 1) == 0) accN0 += lg; else accN1 += lg;                          \
    }                                                                               \
    np4 = np3 + __shfl_xor_sync(FULLM, np3, 2);                                     \
    np3 = np2 + __shfl_xor_sync(FULLM, np2, 4);                                     \
    np2 = np1 + __shfl_xor_sync(FULLM, np1, 8);                                     \
    np1 = np0 + __shfl_xor_sync(FULLM, np0, 16);                                    \
    np0 = loc;                                                                      \
    if ((FIRST) && (U) == 0) {                                                      \
        e0 = (lane == 0) ? yB : 0.f;                                                \
        o0 = (lane == 0) ? y0 : 0.f;                                                \
    } else {                                                                        \
        /* rotate-by-1 with wraparound: lane 0 gets lane 31 (the broadcast) */      \
        float r0 = __shfl_sync(FULLM, o0, lanem1);                                  \
        float r1 = __shfl_sync(FULLM, o1, lanem1);                                  \
        float r2 = __shfl_sync(FULLM, o2, lanem1);                                  \
        float m0 = (lane == 0) ? 0.f : r0;                                          \
        float m1 = (lane == 0) ? r0 : r1;                                           \
        float m2 = (lane == 0) ? r1 : r2;                                           \
        float ne0 = yB * (e0 + m0);                                                 \
        float ne1 = yB * (e1 + m1);                                                 \
        float ne2 = yB * (e2 + m2);                                                 \
        float no0 = y0 * __fmaf_rn(al0, m0, o0 + e0);                               \
        float no1 = y1 * __fmaf_rn(al1, m1, o1 + e1);                               \
        float no2 = y2 * __fmaf_rn(al2, m2, o2 + e2);                               \
        e0 = ne0; e1 = ne1; e2 = ne2; o0 = no0; o1 = no1; o2 = no2;                 \
    }                                                                               \
    /* lagged rescale: one butterfly stage per step, applied at U==7 */             \
    if ((U) == 0)      { rs = ((e0 + e1) + (e2 + o0)) + (o1 + o2); }                \
    else if ((U) == 1) { rs += __shfl_xor_sync(FULLM, rs, 16); }                    \
    else if ((U) == 2) { rs += __shfl_xor_sync(FULLM, rs, 8); }                     \
    else if ((U) == 3) { rs += __shfl_xor_sync(FULLM, rs, 4); }                     \
    else if ((U) == 4) { rs += __shfl_xor_sync(FULLM, rs, 2); }                     \
    else if ((U) == 5) { rs += __shfl_xor_sync(FULLM, rs, 1); }                     \
    else if ((U) == 6) { pend = __logf(rs); cN = __fdividef(1.f, rs); }             \
    else               { e0 *= cN; e1 *= cN; e2 *= cN;                              \
                         o0 *= cN; o1 *= cN; o2 *= cN; accS += pend; }              \
    rp = rn;                                                                        \
    t++;                                                                            \
} while (0)

    CTC_STEP(1, 0); CTC_STEP(1, 1); CTC_STEP(1, 2); CTC_STEP(1, 3);
    CTC_STEP(1, 4); CTC_STEP(1, 5); CTC_STEP(1, 6); CTC_STEP(1, 7);

#pragma unroll 1
    for (int g = 1; g < TT / 8; g++) {
        CTC_STEP(0, 0); CTC_STEP(0, 1); CTC_STEP(0, 2); CTC_STEP(0, 3);
        CTC_STEP(0, 4); CTC_STEP(0, 5); CTC_STEP(0, 6); CTC_STEP(0, 7);
    }
#undef CTC_STEP

    // drain norm pipeline (rows TT-5 .. TT-1)
#pragma unroll
    for (int d = 0; d < 5; d++) {
        float fin = np4 + __shfl_xor_sync(FULLM, np4, 1);
        float lg = __logf(fin + (float)CC * FEPS);
        if ((d & 1) == 0) accN0 += lg; else accN1 += lg;
        np4 = np3 + __shfl_xor_sync(FULLM, np3, 2);
        np3 = np2 + __shfl_xor_sync(FULLM, np2, 4);
        np2 = np1 + __shfl_xor_sync(FULLM, np1, 8);
        np1 = np0 + __shfl_xor_sync(FULLM, np0, 16);
        np0 = 0.f;
    }

    // tail: states 160 (e_80 = e2@lane16) and 159 (o_79 = o2@lane15)
    float accN = accN0 + accN1;
    float e80 = __shfl_sync(FULLM, e2, 16);
    float o79 = __shfl_sync(FULLM, o2, 15);
    if (lane == 0) {
        out[b] = -(__logf(e80 + o79) + accS - accN);
    }
}

extern "C" void kernel_launch(void* const* d_in, const int* in_sizes, int n_in,
                              void* d_out, int out_size) {
    (void)in_sizes; (void)n_in; (void)out_size;
    const int* labels = (const int*)d_in[0];
    const float* ypred = (const float*)d_in[1];
    float* out = (float*)d_out;
    const int smem = 4 * RING * CC * (int)sizeof(float);   // 96 KB
    cudaFuncSetAttribute(ctc_kernel, cudaFuncAttributeMaxDynamicSharedMemorySize, smem);
    ctc_kernel<<<128, 128, smem>>>(labels, ypred, out);
}

// round 17
// speedup vs baseline: 1.2104x; 1.2104x over previous
#include <cuda_runtime.h>
#include <cstdint>
#include <cstddef>

#define TT 512
#define CC 128
#define LL 80
#define BLANKC 127
#define FEPS 1e-7f
#define FULLM 0xffffffffu
#define RING 32
#define NGRP 3
#define PRIME 24

__device__ __forceinline__ void cp_async16(void* smem, const void* gmem) {
    unsigned s = (unsigned)__cvta_generic_to_shared(smem);
    asm volatile("cp.async.ca.shared.global [%0], [%1], 16;\n" :: "r"(s), "l"(gmem));
}
__device__ __forceinline__ void cp_commit() {
    asm volatile("cp.async.commit_group;\n" ::: "memory");
}
__device__ __forceinline__ void cp_waitg() {
    asm volatile("cp.async.wait_group %0;\n" :: "n"(NGRP - 1) : "memory");
}

// 128 blocks x 128 threads: one warp per SMSP, one batch element per warp.
// R13 core (32-row cp.async ring, 8-row commit groups, 3 in flight, gather
// prefetch one step ahead, rotate-shfl recursion, linear domain + 8-step
// lagged rescale) with the norm butterfly replaced by a TRANSPOSED norm:
// during group g (steps 8g..8g+7; rows 8g..8g+7 complete at the group wait),
// lane l = 8a+r privately sums row 8g+nr, one float4/step at chunk
// a*8 + ((U+r)&7) (rotation keeps the LDS at the conflict-free 4 phases; the
// 4 lanes per row cover disjoint chunk windows). Group end: shfl_xor 8,16
// fuse the 4 partials, one log per lane (lane r owns rows == r mod 8), and
// the row slot advances via a MASKED integer slot (nslot = (nslot+8)&31 —
// the pointer-equality wrap in the previous round missed for r>0 and walked
// off the allocation). 3-shfl reduce of accN after the loop.
// States: e_i = alpha[2i] (blank, i=0..80) lane i%32 reg i/32; o_i likewise.
__global__ void __launch_bounds__(128, 1) ctc_kernel(
    const int* __restrict__ lab32,
    const float* __restrict__ ypred,
    float* __restrict__ out)
{
    extern __shared__ __align__(16) float ring[];   // [4][RING][CC] = 64 KB
    const int lane = threadIdx.x & 31;
    const int w = threadIdx.x >> 5;
    const int b = blockIdx.x * 4 + w;
    const int lanem1 = (lane + 31) & 31;
    const int nr = lane & 7;          // norm row-within-group
    const int na = lane >> 3;         // norm chunk-window index (0..3)
    float* __restrict__ rw = ring + (size_t)w * RING * CC;
    const float* __restrict__ yb = ypred + (size_t)b * (TT * CC);

    // detect label element width (int64 little-endian vs int32)
    int probe = lab32[1] | lab32[3] | lab32[5] | lab32[7]
              | lab32[9] | lab32[11] | lab32[13] | lab32[15];
    const int stride = (probe == 0) ? 2 : 1;
    const int* lb = lab32 + (size_t)b * LL * stride;

    const int i1 = 32 + lane, i2 = 64 + lane;
    const int L0 = lb[lane * stride];
    const int L1 = lb[i1 * stride];
    const bool v2 = (i2 < LL);
    const int L2 = v2 ? lb[i2 * stride] : BLANKC;
    const float al0 = (lane == 0) ? 0.f : ((L0 != lb[(lane - 1) * stride]) ? 1.f : 0.f);
    const float al1 = (L1 != lb[(i1 - 1) * stride]) ? 1.f : 0.f;
    const float al2 = (v2 && (L2 != lb[(i2 - 1) * stride])) ? 1.f : 0.f;

    // prime NGRP groups: rows 0..PRIME-1
#pragma unroll
    for (int g = 0; g < NGRP; g++) {
#pragma unroll
        for (int r = 0; r < 8; r++) {
            int row = g * 8 + r;
            cp_async16(rw + row * CC + lane * 4, yb + (size_t)row * CC + lane * 4);
        }
        cp_commit();
    }

    float e0 = 0.f, e1 = 0.f, e2 = 0.f, o0 = 0.f, o1 = 0.f, o2 = 0.f;
    float accN = 0.f, accS = 0.f, rowsum = 0.f;
    float rs = 0.f, pend = 0.f, cN = 1.f;
    float pB = 0.f, p0 = 0.f, p1 = 0.f, p2 = 0.f;   // gather prefetch regs

    // norm state: masked slot index of this lane's current row (row 8g+nr)
    int nslot = nr;
    const float* winb = rw + nslot * CC + na * 32;  // window start (8 chunks)
    const float* wine = winb + 32;
    const float* nq = winb + nr * 4;                // chunk a*8 + ((0+nr)&7)

    int t = 0;

#define CTC_STEP(FIRST, U) do {                                                     \
    float yB, y0, y1, y2;                                                           \
    if ((U) == 0) {                                                                 \
        cp_waitg();                                                                 \
        __syncwarp();                                                               \
        _Pragma("unroll")                                                           \
        for (int j = 0; j < 8; j++) {                                               \
            int tn = t + PRIME + j;                                                 \
            if (tn < TT)                                                            \
                cp_async16(rw + ((tn & (RING - 1)) * CC) + lane * 4,                \
                           yb + (size_t)tn * CC + lane * 4);                        \
        }                                                                           \
        cp_commit();                                                                \
        const float* rg = rw + ((t & (RING - 1)) * CC);                             \
        yB = rg[BLANKC] + FEPS;                                                     \
        y0 = rg[L0] + FEPS;                                                         \
        y1 = rg[L1] + FEPS;                                                         \
        y2 = v2 ? (rg[L2] + FEPS) : 0.f;                                            \
    } else {                                                                        \
        yB = pB + FEPS;                                                             \
        y0 = p0 + FEPS;                                                             \
        y1 = p1 + FEPS;                                                             \
        y2 = v2 ? (p2 + FEPS) : 0.f;                                                \
    }                                                                               \
    if ((U) < 7) {                                                                  \
        const float* rn = rw + (((t + 1) & (RING - 1)) * CC);                       \
        pB = rn[BLANKC]; p0 = rn[L0]; p1 = rn[L1]; p2 = rn[L2];                     \
    }                                                                               \
    /* transposed norm: one float4 of this lane's private row */                    \
    {                                                                               \
        float4 nv = *(const float4*)nq;                                             \
        float s4 = (nv.x + nv.y) + (nv.z + nv.w);                                   \
        if ((U) == 0) rowsum = s4; else rowsum += s4;                               \
        const float* nq2 = nq + 4;                                                  \
        nq = (nq2 == wine) ? winb : nq2;                                            \
    }                                                                               \
    if ((FIRST) && (U) == 0) {                                                      \
        e0 = (lane == 0) ? yB : 0.f;                                                \
        o0 = (lane == 0) ? y0 : 0.f;                                                \
    } else {                                                                        \
        /* rotate-by-1 with wraparound: lane 0 gets lane 31 (the broadcast) */      \
        float r0 = __shfl_sync(FULLM, o0, lanem1);                                  \
        float r1 = __shfl_sync(FULLM, o1, lanem1);                                  \
        float r2 = __shfl_sync(FULLM, o2, lanem1);                                  \
        float m0 = (lane == 0) ? 0.f : r0;                                          \
        float m1 = (lane == 0) ? r0 : r1;                                           \
        float m2 = (lane == 0) ? r1 : r2;                                           \
        float ne0 = yB * (e0 + m0);                                                 \
        float ne1 = yB * (e1 + m1);                                                 \
        float ne2 = yB * (e2 + m2);                                                 \
        float no0 = y0 * __fmaf_rn(al0, m0, o0 + e0);                               \
        float no1 = y1 * __fmaf_rn(al1, m1, o1 + e1);                               \
        float no2 = y2 * __fmaf_rn(al2, m2, o2 + e2);                               \
        e0 = ne0; e1 = ne1; e2 = ne2; o0 = no0; o1 = no1; o2 = no2;                 \
    }                                                                               \
    /* lagged rescale: one butterfly stage per step, applied at U==7 */             \
    if ((U) == 0)      { rs = ((e0 + e1) + (e2 + o0)) + (o1 + o2); }                \
    else if ((U) == 1) { rs += __shfl_xor_sync(FULLM, rs, 16); }                    \
    else if ((U) == 2) { rs += __shfl_xor_sync(FULLM, rs, 8); }                     \
    else if ((U) == 3) { rs += __shfl_xor_sync(FULLM, rs, 4); }                     \
    else if ((U) == 4) { rs += __shfl_xor_sync(FULLM, rs, 2); }                     \
    else if ((U) == 5) { rs += __shfl_xor_sync(FULLM, rs, 1); }                     \
    else if ((U) == 6) { pend = __logf(rs); cN = __fdividef(1.f, rs); }             \
    else {                                                                          \
        e0 *= cN; e1 *= cN; e2 *= cN;                                               \
        o0 *= cN; o1 *= cN; o2 *= cN;                                               \
        accS += pend;                                                               \
        /* norm group end: fuse 4 partials, log, advance row (masked slot) */       \
        float tot = rowsum;                                                         \
        tot += __shfl_xor_sync(FULLM, tot, 8);                                      \
        tot += __shfl_xor_sync(FULLM, tot, 16);                                     \
        accN += __logf(tot + (float)CC * FEPS);                                     \
        nslot = (nslot + 8) & (RING - 1);                                           \
        winb = rw + nslot * CC + na * 32; wine = winb + 32;                         \
        nq = winb + nr * 4;                                                         \
    }                                                                               \
    t++;                                                                            \
} while (0)

    CTC_STEP(1, 0); CTC_STEP(1, 1); CTC_STEP(1, 2); CTC_STEP(1, 3);
    CTC_STEP(1, 4); CTC_STEP(1, 5); CTC_STEP(1, 6); CTC_STEP(1, 7);

#pragma unroll 1
    for (int g = 1; g < TT / 8; g++) {
        CTC_STEP(0, 0); CTC_STEP(0, 1); CTC_STEP(0, 2); CTC_STEP(0, 3);
        CTC_STEP(0, 4); CTC_STEP(0, 5); CTC_STEP(0, 6); CTC_STEP(0, 7);
    }
#undef CTC_STEP

    // reduce accN: lanes 0..7 hold per-r log sums (lanes 8a+r duplicate);
    // xor 4,2,1 gives lane 0 the sum over r = 0..7.
    accN += __shfl_xor_sync(FULLM, accN, 4);
    accN += __shfl_xor_sync(FULLM, accN, 2);
    accN += __shfl_xor_sync(FULLM, accN, 1);

    // tail: states 160 (e_80 = e2@lane16) and 159 (o_79 = o2@lane15)
    float e80 = __shfl_sync(FULLM, e2, 16);
    float o79 = __shfl_sync(FULLM, o2, 15);
    if (lane == 0) {
        out[b] = -(__logf(e80 + o79) + accS - accN);
    }
}

extern "C" void kernel_launch(void* const* d_in, const int* in_sizes, int n_in,
                              void* d_out, int out_size) {
    (void)in_sizes; (void)n_in; (void)out_size;
    const int* labels = (const int*)d_in[0];
    const float* ypred = (const float*)d_in[1];
    float* out = (float*)d_out;
    const int smem = 4 * RING * CC * (int)sizeof(float);   // 64 KB
    cudaFuncSetAttribute(ctc_kernel, cudaFuncAttributeMaxDynamicSharedMemorySize, smem);
    ctc_kernel<<<128, 128, smem>>>(labels, ypred, out);
}